// round 6
// baseline (speedup 1.0000x reference)
#include <cuda_runtime.h>
#include <cstdint>

#define BH   32
#define SEQ  2048
#define DH   128
#define BM   128
#define TK   64
#define NT   (SEQ / TK)
#define N_ELEM (2 * 16 * 2048 * 128)

typedef uint32_t u32;

// ---- SMEM byte offsets ----
#define SQ       0                        // Q: 128 rows x 512B = 65536
#define SKOFF(b) (65536 + (b) * 32768)    // K: 2 x (64 rows x 512B)
#define SVOFF(b) (131072 + (b) * 32768)   // V^T: 2 x (128 rows x 256B)
#define SS       196608                   // S: 128 rows x 256B = 32768
#define SMEM_TOTAL 229376

__device__ float g_scr[3 * N_ELEM];   // tf32 Q*scale, K, V^T

__device__ __forceinline__ float to_tf32(float x) {
    u32 u;
    asm("cvt.rna.tf32.f32 %0, %1;" : "=r"(u) : "f"(x));
    return __uint_as_float(u);
}
__device__ __forceinline__ void mma8(float* c,
                                     u32 a0, u32 a1, u32 a2, u32 a3,
                                     u32 b0, u32 b1) {
    asm volatile(
        "mma.sync.aligned.m16n8k8.row.col.f32.tf32.tf32.f32 "
        "{%0,%1,%2,%3},{%4,%5,%6,%7},{%8,%9},{%0,%1,%2,%3};\n"
        : "+f"(c[0]), "+f"(c[1]), "+f"(c[2]), "+f"(c[3])
        : "r"(a0), "r"(a1), "r"(a2), "r"(a3), "r"(b0), "r"(b1));
}
#define FU __float_as_uint
#define CP16(dst, src) \
    asm volatile("cp.async.cg.shared.global [%0], [%1], 16;" :: "r"(dst), "l"(src))
#define CP_COMMIT() asm volatile("cp.async.commit_group;" ::: "memory")
#define CP_WAIT(n)  asm volatile("cp.async.wait_group %0;" :: "n"(n) : "memory")

// ---------------- prepass 1: round Q (x scale) and K to tf32 ----------------
__global__ void __launch_bounds__(256)
prepass_qk(const float* __restrict__ q, const float* __restrict__ k,
           const float* __restrict__ sc) {
    const float scale = *sc;
    const int n4 = N_ELEM / 4;
    float4* dq = (float4*)g_scr;
    float4* dk = (float4*)(g_scr + N_ELEM);
    for (int i = blockIdx.x * blockDim.x + threadIdx.x; i < n4;
         i += gridDim.x * blockDim.x) {
        float4 a = ((const float4*)q)[i];
        a.x = to_tf32(a.x * scale); a.y = to_tf32(a.y * scale);
        a.z = to_tf32(a.z * scale); a.w = to_tf32(a.w * scale);
        dq[i] = a;
        float4 b = ((const float4*)k)[i];
        b.x = to_tf32(b.x); b.y = to_tf32(b.y);
        b.z = to_tf32(b.z); b.w = to_tf32(b.w);
        dk[i] = b;
    }
}

// ---------------- prepass 2: V -> V^T ([bh][d][s]) tf32 ----------------
__global__ void __launch_bounds__(256)
prepass_vt(const float* __restrict__ v) {
    __shared__ float tile[32][33];
    const int bh = blockIdx.z;
    const int s0 = blockIdx.x * 32, d0 = blockIdx.y * 32;
    const float* vin = v + (size_t)bh * SEQ * DH;
    float* vout = g_scr + 2 * N_ELEM + (size_t)bh * SEQ * DH;
    const int tx = threadIdx.x, ty = threadIdx.y;
    #pragma unroll
    for (int j = 0; j < 32; j += 8)
        tile[ty + j][tx] = vin[(size_t)(s0 + ty + j) * DH + d0 + tx];
    __syncthreads();
    #pragma unroll
    for (int j = 0; j < 32; j += 8)
        vout[(size_t)(d0 + ty + j) * SEQ + s0 + tx] = to_tf32(tile[tx][ty + j]);
}

// ---------------- cp.async tile loaders ----------------
// K-major 512B rows (Q/K): chunk c4 stored at c4 ^ ((r&1)<<2)
__device__ __forceinline__ void cp_kmaj(u32 smbase, const float* __restrict__ g,
                                        int rows, int tid) {
    const int n = rows * 32;
    for (int idx = tid; idx < n; idx += 512) {
        int r = idx >> 5, c4 = idx & 31;
        u32 dst = smbase + r * 512 + ((c4 ^ ((r & 1) << 2)) << 4);
        CP16(dst, g + r * DH + c4 * 4);
    }
}
// V^T tile: 128 rows (d) x 256B (64 kv floats); chunk c4 ^ s(r&7),
// s(r) = ((r&1)<<2) | ((r>>1)&3)  -> conflict-free LDS.128 phases
__device__ __forceinline__ void cp_vt(u32 smbase, const float* __restrict__ gvt,
                                      int tid) {
    for (int idx = tid; idx < 128 * 16; idx += 512) {
        int r = idx >> 4, c4 = idx & 15;
        int s = ((r & 1) << 2) | ((r >> 1) & 3);
        u32 dst = smbase + r * 256 + ((c4 ^ s) << 4);
        CP16(dst, gvt + (size_t)r * SEQ + c4 * 4);
    }
}

// ---------------- main fused kernel: 512 threads ----------------
__global__ void __launch_bounds__(512, 1)
attn_relu2_kernel(float* __restrict__ out) {
    extern __shared__ char smp[];
    u32 sb;
    asm("{ .reg .u64 t; cvta.to.shared.u64 t, %1; cvt.u32.u64 %0, t; }"
        : "=r"(sb) : "l"(smp));

    const int tid  = threadIdx.x;
    const int lane = tid & 31;
    const int warp = tid >> 5;
    const int g = lane >> 2;
    const int t = lane & 3;
    const int wm = warp & 3;    // 4 m-strips of 32 rows
    const int wn = warp >> 2;   // 4 n-strips

    const int bh = blockIdx.y;
    const int q0 = blockIdx.x * BM;
    const size_t base = (size_t)bh * SEQ * DH;

    const float* qs  = g_scr + base + (size_t)q0 * DH;
    const float* ks  = g_scr + N_ELEM + base;
    const float* vts = g_scr + 2 * N_ELEM + base;   // [d][s]

    const int axor = (g & 1) << 2;
    const int svt  = ((g & 1) << 2) | ((g >> 1) & 3);

    // ---- prologue ----
    cp_kmaj(sb + SQ, qs, 128, tid);
    cp_kmaj(sb + SKOFF(0), ks, 64, tid);
    cp_vt(sb + SVOFF(0), vts, tid);
    CP_COMMIT();

    float oacc[2][4][4];
    #pragma unroll
    for (int a = 0; a < 2; a++)
        #pragma unroll
        for (int b = 0; b < 4; b++)
            #pragma unroll
            for (int c = 0; c < 4; c++) oacc[a][b][c] = 0.f;

    for (int i = 0; i < NT; i++) {
        const int b = i & 1;
        __syncthreads();   // retire reads of buf b^1 and S

        if (i + 1 < NT) {
            cp_kmaj(sb + SKOFF(b ^ 1), ks + (size_t)(i + 1) * TK * DH, 64, tid);
            cp_vt(sb + SVOFF(b ^ 1), vts + (size_t)(i + 1) * TK, tid);
            CP_COMMIT();
            CP_WAIT(1);
        } else {
            CP_WAIT(0);
        }
        __syncthreads();   // tile i visible

        // ---- GEMM1: S[128x64] = Q @ K^T (warp tile 32x16) ----
        float sacc[2][2][4];
        #pragma unroll
        for (int a = 0; a < 2; a++)
            #pragma unroll
            for (int bb = 0; bb < 2; bb++)
                #pragma unroll
                for (int c = 0; c < 4; c++) sacc[a][bb][c] = 0.f;

        #pragma unroll
        for (int kc = 0; kc < 8; kc++) {
            const int gsel = ((kc * 4 + t) ^ axor) << 4;
            float4 Bf[2];
            #pragma unroll
            for (int ni = 0; ni < 2; ni++) {
                int rb = wn * 16 + ni * 8 + g;
                Bf[ni] = *(const float4*)(smp + SKOFF(b) + rb * 512 + gsel);
            }
            float4 Af[2][2];
            #pragma unroll
            for (int mi = 0; mi < 2; mi++) {
                int r0 = wm * 32 + mi * 16 + g;
                Af[mi][0] = *(const float4*)(smp + SQ + r0 * 512 + gsel);
                Af[mi][1] = *(const float4*)(smp + SQ + (r0 + 8) * 512 + gsel);
            }
            #pragma unroll
            for (int mi = 0; mi < 2; mi++)
                #pragma unroll
                for (int ni = 0; ni < 2; ni++) {
                    mma8(sacc[mi][ni],
                         FU(Af[mi][0].x), FU(Af[mi][1].x),
                         FU(Af[mi][0].y), FU(Af[mi][1].y),
                         FU(Bf[ni].x), FU(Bf[ni].y));
                    mma8(sacc[mi][ni],
                         FU(Af[mi][0].z), FU(Af[mi][1].z),
                         FU(Af[mi][0].w), FU(Af[mi][1].w),
                         FU(Bf[ni].z), FU(Bf[ni].w));
                }
        }

        // ---- epilogue: relu(s)^2 -> tf32 -> S smem ----
        #pragma unroll
        for (int mi = 0; mi < 2; mi++) {
            #pragma unroll
            for (int ni = 0; ni < 2; ni++) {
                const int col = wn * 16 + ni * 8 + 2 * t;
                const int lc = col >> 2;
                const int sub = (col & 3) * 4;
                float e[4];
                #pragma unroll
                for (int j = 0; j < 4; j++) {
                    float x = fmaxf(sacc[mi][ni][j], 0.f);
                    e[j] = to_tf32(x * x);
                }
                const int r0 = wm * 32 + mi * 16 + g;
                *(float2*)(smp + SS + r0 * 256 + ((lc ^ axor) << 4) + sub) =
                    make_float2(e[0], e[1]);
                *(float2*)(smp + SS + (r0 + 8) * 256 + ((lc ^ axor) << 4) + sub) =
                    make_float2(e[2], e[3]);
            }
        }
        __syncthreads();   // S visible

        // ---- GEMM2: O += S @ V  (warp tile 32x32, B from V^T) ----
        #pragma unroll
        for (int kc = 0; kc < 4; kc++) {
            const int gsel = ((kc * 4 + t) ^ axor) << 4;
            float4 As[2][2];
            #pragma unroll
            for (int mi = 0; mi < 2; mi++) {
                int r0 = wm * 32 + mi * 16 + g;
                As[mi][0] = *(const float4*)(smp + SS + r0 * 256 + gsel);
                As[mi][1] = *(const float4*)(smp + SS + (r0 + 8) * 256 + gsel);
            }
            const int vsel = ((kc * 4 + t) ^ svt) << 4;
            float4 Bv[4];
            #pragma unroll
            for (int nj = 0; nj < 4; nj++) {
                int rb = wn * 32 + nj * 8 + g;
                Bv[nj] = *(const float4*)(smp + SVOFF(b) + rb * 256 + vsel);
            }
            #pragma unroll
            for (int mi = 0; mi < 2; mi++)
                #pragma unroll
                for (int nj = 0; nj < 4; nj++) {
                    mma8(oacc[mi][nj],
                         FU(As[mi][0].x), FU(As[mi][1].x),
                         FU(As[mi][0].y), FU(As[mi][1].y),
                         FU(Bv[nj].x), FU(Bv[nj].y));
                    mma8(oacc[mi][nj],
                         FU(As[mi][0].z), FU(As[mi][1].z),
                         FU(As[mi][0].w), FU(As[mi][1].w),
                         FU(Bv[nj].z), FU(Bv[nj].w));
                }
        }
    }

    // ---- write O ----
    float* og = out + base + (size_t)q0 * DH;
    #pragma unroll
    for (int mi = 0; mi < 2; mi++) {
        #pragma unroll
        for (int nj = 0; nj < 4; nj++) {
            int r0 = wm * 32 + mi * 16 + g;
            int col = wn * 32 + nj * 8 + 2 * t;
            *(float2*)(og + (size_t)r0 * DH + col) =
                make_float2(oacc[mi][nj][0], oacc[mi][nj][1]);
            *(float2*)(og + (size_t)(r0 + 8) * DH + col) =
                make_float2(oacc[mi][nj][2], oacc[mi][nj][3]);
        }
    }
}

extern "C" void kernel_launch(void* const* d_in, const int* in_sizes, int n_in,
                              void* d_out, int out_size) {
    const float* q  = (const float*)d_in[0];
    const float* k  = (const float*)d_in[1];
    const float* v  = (const float*)d_in[2];
    const float* sc = (const float*)d_in[3];
    float* out = (float*)d_out;

    prepass_qk<<<1024, 256>>>(q, k, sc);
    dim3 tgrid(SEQ / 32, DH / 32, BH);
    prepass_vt<<<tgrid, dim3(32, 8)>>>(v);

    cudaFuncSetAttribute(attn_relu2_kernel,
                         cudaFuncAttributeMaxDynamicSharedMemorySize, SMEM_TOTAL);
    dim3 grid(SEQ / BM, BH);
    attn_relu2_kernel<<<grid, 512, SMEM_TOTAL>>>(out);
}